// round 1
// baseline (speedup 1.0000x reference)
#include <cuda_runtime.h>

#define NN 50000
#define DD 128
#define D2 256
#define NE 600000
#define NL 5

// ---------------- device scratch (static, no runtime allocation) ----------------
__device__ __align__(16) float g_h[NN * DD];     // node features (layer input)
__device__ __align__(16) float g_z[NN * DD];     // z = (1+eps)h + agg; later reused as z2
__device__ __align__(16) float g_y[NN * D2];     // hidden after Linear1
__device__ __align__(16) float g_stats[2 * D2];  // [0:ncols) colsum, [256:256+ncols) colsumsq
__device__ __align__(16) float g_sc[D2];         // BN scale  (g * istd)
__device__ __align__(16) float g_sh[D2];         // BN shift  (be - mu * g * istd)

// ---------------- atom encoder: h[n,d] = sum_k atom_emb[k, x[n,k], d] ----------------
__global__ void atom_enc_kernel(const int* __restrict__ x, const float* __restrict__ emb) {
    int i = blockIdx.x * blockDim.x + threadIdx.x;  // over NN*DD
    int n = i >> 7;
    int d = i & 127;
    float s = 0.f;
#pragma unroll
    for (int k = 0; k < 9; k++) {
        int v = x[n * 9 + k];
        s += emb[((size_t)(k * 128 + v)) * 128 + d];
    }
    g_h[i] = s;
}

// ---------------- z = (1 + eps_l) * h ----------------
__global__ void init_z_kernel(const float* __restrict__ eps_l) {
    int i = blockIdx.x * blockDim.x + threadIdx.x;
    g_z[i] = (1.f + eps_l[0]) * g_h[i];
}

// ---------------- edge scatter: z[dst] += relu(h[src] + ee) ----------------
// one warp per edge, float4 per lane (32*4 = 128 = D)
__global__ void scatter_kernel(const int* __restrict__ ei, const int* __restrict__ ea,
                               const float* __restrict__ be) {
    int gw   = (blockIdx.x * blockDim.x + threadIdx.x) >> 5;
    int lane = threadIdx.x & 31;
    if (gw >= NE) return;
    int src = ei[gw];
    int dst = ei[NE + gw];
    int a0 = ea[gw * 3 + 0];
    int a1 = ea[gw * 3 + 1];
    int a2 = ea[gw * 3 + 2];
    float4 e0 = ((const float4*)(be + (0 * 8 + a0) * DD))[lane];
    float4 e1 = ((const float4*)(be + (1 * 8 + a1) * DD))[lane];
    float4 e2 = ((const float4*)(be + (2 * 8 + a2) * DD))[lane];
    float4 hv = ((const float4*)(g_h + (size_t)src * DD))[lane];
    float4 m;
    m.x = fmaxf(hv.x + e0.x + e1.x + e2.x, 0.f);
    m.y = fmaxf(hv.y + e0.y + e1.y + e2.y, 0.f);
    m.z = fmaxf(hv.z + e0.z + e1.z + e2.z, 0.f);
    m.w = fmaxf(hv.w + e0.w + e1.w + e2.w, 0.f);
    atomicAdd((float4*)(g_z + (size_t)dst * DD + lane * 4), m);
}

// ---------------- GEMM1: y = z @ W1 + b1   ([NN,128] x [128,256]) ----------------
// block: 512 threads, M-tile 128. smem: W[128][256] + Z[128][128] = 192KB.
__global__ void __launch_bounds__(512, 1)
gemm1_kernel(const float* __restrict__ W, const float* __restrict__ bias) {
    extern __shared__ float sm[];
    float* sW = sm;            // [128][256]
    float* sZ = sm + DD * D2;  // [128][128]
    const int t    = threadIdx.x;
    const int row0 = blockIdx.x * 128;

    const float4* Wv  = (const float4*)W;
    float4*       sWv = (float4*)sW;
#pragma unroll
    for (int i = 0; i < 16; i++) sWv[i * 512 + t] = Wv[i * 512 + t];

    float4* sZv = (float4*)sZ;
#pragma unroll
    for (int i = 0; i < 8; i++) {
        int    idx = i * 512 + t;  // 4096 float4 = 128 rows x 32 f4
        int    r   = idx >> 5;
        int    k4  = idx & 31;
        float4 v   = make_float4(0.f, 0.f, 0.f, 0.f);
        if (row0 + r < NN) v = ((const float4*)g_z)[(size_t)(row0 + r) * 32 + k4];
        sZv[idx] = v;
    }
    __syncthreads();

    const int tx = t & 15;  // cols: {g*64 + tx*4 .. +3}, g=0..3
    const int ty = t >> 4;  // rows: ty*4 .. +3   (ty 0..31)

    float acc[4][16];
#pragma unroll
    for (int i = 0; i < 4; i++)
#pragma unroll
        for (int j = 0; j < 16; j++) acc[i][j] = 0.f;

    for (int k = 0; k < DD; k += 4) {
        float4 a[4];
#pragma unroll
        for (int i = 0; i < 4; i++) a[i] = *(const float4*)(sZ + (ty * 4 + i) * DD + k);
#pragma unroll
        for (int kk = 0; kk < 4; kk++) {
            float4 w[4];
#pragma unroll
            for (int g = 0; g < 4; g++)
                w[g] = *(const float4*)(sW + (k + kk) * D2 + g * 64 + tx * 4);
#pragma unroll
            for (int i = 0; i < 4; i++) {
                float ai = (kk == 0) ? a[i].x : (kk == 1) ? a[i].y : (kk == 2) ? a[i].z : a[i].w;
#pragma unroll
                for (int g = 0; g < 4; g++) {
                    acc[i][g * 4 + 0] += ai * w[g].x;
                    acc[i][g * 4 + 1] += ai * w[g].y;
                    acc[i][g * 4 + 2] += ai * w[g].z;
                    acc[i][g * 4 + 3] += ai * w[g].w;
                }
            }
        }
    }

#pragma unroll
    for (int i = 0; i < 4; i++) {
        int r = row0 + ty * 4 + i;
        if (r < NN) {
#pragma unroll
            for (int g = 0; g < 4; g++) {
                int    c = g * 64 + tx * 4;
                float4 o;
                o.x = acc[i][g * 4 + 0] + bias[c + 0];
                o.y = acc[i][g * 4 + 1] + bias[c + 1];
                o.z = acc[i][g * 4 + 2] + bias[c + 2];
                o.w = acc[i][g * 4 + 3] + bias[c + 3];
                *(float4*)(g_y + (size_t)r * D2 + c) = o;
            }
        }
    }
}

// ---------------- GEMM2: z2 = relu(bn1(y)) @ W2 + b2  ([NN,256] x [256,128]) ----------------
// block: 512 threads, M-tile 64. smem: W[256][128] + A[64][256] = 192KB.
// BN1 scale/shift + relu applied while staging y into smem.
__global__ void __launch_bounds__(512, 1)
gemm2_kernel(const float* __restrict__ W, const float* __restrict__ bias) {
    extern __shared__ float sm[];
    float* sW = sm;            // [256][128]
    float* sA = sm + D2 * DD;  // [64][256]
    const int t    = threadIdx.x;
    const int row0 = blockIdx.x * 64;

    const float4* Wv  = (const float4*)W;
    float4*       sWv = (float4*)sW;
#pragma unroll
    for (int i = 0; i < 16; i++) sWv[i * 512 + t] = Wv[i * 512 + t];

#pragma unroll
    for (int i = 0; i < 8; i++) {
        int    idx = i * 512 + t;  // 4096 f4 = 64 rows x 64 f4
        int    r   = idx >> 6;
        int    c4  = idx & 63;
        float4 v   = make_float4(0.f, 0.f, 0.f, 0.f);
        if (row0 + r < NN) {
            v     = ((const float4*)g_y)[(size_t)(row0 + r) * 64 + c4];
            int c = c4 * 4;
            v.x   = fmaxf(v.x * g_sc[c + 0] + g_sh[c + 0], 0.f);
            v.y   = fmaxf(v.y * g_sc[c + 1] + g_sh[c + 1], 0.f);
            v.z   = fmaxf(v.z * g_sc[c + 2] + g_sh[c + 2], 0.f);
            v.w   = fmaxf(v.w * g_sc[c + 3] + g_sh[c + 3], 0.f);
        }
        ((float4*)sA)[idx] = v;
    }
    __syncthreads();

    const int tx = t & 31;  // cols tx*4..+3
    const int ty = t >> 5;  // rows ty*4..+3 (ty 0..15)

    float acc[4][4];
#pragma unroll
    for (int i = 0; i < 4; i++)
#pragma unroll
        for (int j = 0; j < 4; j++) acc[i][j] = 0.f;

    for (int k = 0; k < D2; k += 4) {
        float4 a[4];
#pragma unroll
        for (int i = 0; i < 4; i++) a[i] = *(const float4*)(sA + (ty * 4 + i) * D2 + k);
#pragma unroll
        for (int kk = 0; kk < 4; kk++) {
            float4 w = *(const float4*)(sW + (k + kk) * DD + tx * 4);
#pragma unroll
            for (int i = 0; i < 4; i++) {
                float ai = (kk == 0) ? a[i].x : (kk == 1) ? a[i].y : (kk == 2) ? a[i].z : a[i].w;
                acc[i][0] += ai * w.x;
                acc[i][1] += ai * w.y;
                acc[i][2] += ai * w.z;
                acc[i][3] += ai * w.w;
            }
        }
    }

#pragma unroll
    for (int i = 0; i < 4; i++) {
        int r = row0 + ty * 4 + i;
        if (r < NN) {
            int    c = tx * 4;
            float4 o;
            o.x = acc[i][0] + bias[c + 0];
            o.y = acc[i][1] + bias[c + 1];
            o.z = acc[i][2] + bias[c + 2];
            o.w = acc[i][3] + bias[c + 3];
            *(float4*)(g_z + (size_t)r * DD + c) = o;  // z2 overwrites g_z
        }
    }
}

// ---------------- column stats (sum, sumsq) ----------------
__global__ void zero_stats_kernel() { g_stats[threadIdx.x] = 0.f; }

__global__ void colstats_y_kernel() {  // over g_y, 256 cols
    int   c  = threadIdx.x;
    int   r0 = blockIdx.x * 128;
    float s = 0.f, q = 0.f;
    for (int i = 0; i < 128; i++) {
        int r = r0 + i;
        if (r < NN) {
            float v = g_y[(size_t)r * D2 + c];
            s += v;
            q += v * v;
        }
    }
    atomicAdd(&g_stats[c], s);
    atomicAdd(&g_stats[256 + c], q);
}

__global__ void colstats_z_kernel() {  // over g_z, 128 cols
    int   c  = threadIdx.x;
    int   r0 = blockIdx.x * 128;
    float s = 0.f, q = 0.f;
    for (int i = 0; i < 128; i++) {
        int r = r0 + i;
        if (r < NN) {
            float v = g_z[(size_t)r * DD + c];
            s += v;
            q += v * v;
        }
    }
    atomicAdd(&g_stats[c], s);
    atomicAdd(&g_stats[256 + c], q);
}

__global__ void finalize_kernel(const float* __restrict__ g, const float* __restrict__ be,
                                int ncols) {
    int c = threadIdx.x;
    if (c < ncols) {
        float mu   = g_stats[c] * (1.f / NN);
        float var  = g_stats[256 + c] * (1.f / NN) - mu * mu;
        float istd = rsqrtf(var + 1e-5f);
        float s    = g[c] * istd;
        g_sc[c]    = s;
        g_sh[c]    = be[c] - mu * s;
    }
}

// ---------------- final BN + (relu) -> h or out ----------------
__global__ void norm_out_kernel(float* __restrict__ out, int is_last) {
    int   i = blockIdx.x * blockDim.x + threadIdx.x;
    int   c = i & (DD - 1);
    float v = g_z[i] * g_sc[c] + g_sh[c];
    if (is_last) {
        out[i] = v;  // no relu on last layer
    } else {
        g_h[i] = fmaxf(v, 0.f);
    }
}

// ---------------- launch ----------------
extern "C" void kernel_launch(void* const* d_in, const int* in_sizes, int n_in,
                              void* d_out, int out_size) {
    const int*   x    = (const int*)d_in[0];
    const int*   ei   = (const int*)d_in[1];
    const int*   ea   = (const int*)d_in[2];
    const float* aemb = (const float*)d_in[3];
    const float* bemb = (const float*)d_in[4];
    const float* W1   = (const float*)d_in[5];
    const float* b1   = (const float*)d_in[6];
    const float* g1   = (const float*)d_in[7];
    const float* be1  = (const float*)d_in[8];
    const float* W2   = (const float*)d_in[9];
    const float* b2   = (const float*)d_in[10];
    const float* eps  = (const float*)d_in[11];
    const float* gout = (const float*)d_in[12];
    const float* beo  = (const float*)d_in[13];
    float*       out  = (float*)d_out;

    const int smem_bytes = (DD * D2 + DD * DD) * 4;  // 192KB for gemm1; same size for gemm2
    cudaFuncSetAttribute(gemm1_kernel, cudaFuncAttributeMaxDynamicSharedMemorySize, smem_bytes);
    cudaFuncSetAttribute(gemm2_kernel, cudaFuncAttributeMaxDynamicSharedMemorySize, smem_bytes);

    atom_enc_kernel<<<(NN * DD) / 256, 256>>>(x, aemb);

    for (int l = 0; l < NL; l++) {
        init_z_kernel<<<(NN * DD) / 256, 256>>>(eps + l);
        scatter_kernel<<<NE / 8, 256>>>(ei, ea, bemb + l * 3 * 8 * DD);

        gemm1_kernel<<<(NN + 127) / 128, 512, smem_bytes>>>(W1 + (size_t)l * DD * D2,
                                                            b1 + l * D2);
        zero_stats_kernel<<<1, 512>>>();
        colstats_y_kernel<<<(NN + 127) / 128, 256>>>();
        finalize_kernel<<<1, 256>>>(g1 + l * D2, be1 + l * D2, D2);

        gemm2_kernel<<<(NN + 63) / 64, 512, smem_bytes>>>(W2 + (size_t)l * D2 * DD,
                                                          b2 + l * DD);
        zero_stats_kernel<<<1, 512>>>();
        colstats_z_kernel<<<(NN + 127) / 128, 128>>>();
        finalize_kernel<<<1, 256>>>(gout + l * DD, beo + l * DD, DD);

        norm_out_kernel<<<(NN * DD) / 256, 256>>>(out, (l == NL - 1) ? 1 : 0);
    }
}

// round 3
// speedup vs baseline: 1.3513x; 1.3513x over previous
#include <cuda_runtime.h>
#include <cuda_bf16.h>
#include <cstdint>

#define NN 50000
#define DD 128
#define D2 256
#define NE 600000
#define NL 5

// ---------------- device scratch ----------------
__device__ __align__(16) float g_h[NN * DD];
__device__ __align__(16) float g_z[NN * DD];
__device__ __align__(16) float g_y[NN * D2];
__device__ float g_stats[2 * D2];
__device__ float g_sc[D2];
__device__ float g_sh[D2];
// per-layer weight transposes in bf16 hi/lo:  w1: [n=256][k=128], w2: [n=128][k=256]
__device__ __align__(16) __nv_bfloat16 g_w1h[D2 * DD];
__device__ __align__(16) __nv_bfloat16 g_w1l[D2 * DD];
__device__ __align__(16) __nv_bfloat16 g_w2h[DD * D2];
__device__ __align__(16) __nv_bfloat16 g_w2l[DD * D2];

// ---------------- mma.sync wrapper (m16n8k16, bf16 x bf16 -> f32) ----------------
__device__ __forceinline__ void mma16816(float* c, const uint32_t* a, const uint32_t* b) {
    asm volatile(
        "mma.sync.aligned.m16n8k16.row.col.f32.bf16.bf16.f32 "
        "{%0,%1,%2,%3}, {%4,%5,%6,%7}, {%8,%9}, {%0,%1,%2,%3};"
        : "+f"(c[0]), "+f"(c[1]), "+f"(c[2]), "+f"(c[3])
        : "r"(a[0]), "r"(a[1]), "r"(a[2]), "r"(a[3]), "r"(b[0]), "r"(b[1]));
}

// split 8 fp32 -> packed bf16 hi/lo (4+4 uint32)
__device__ __forceinline__ void split8(const float* v, uint4& hi, uint4& lo) {
    uint32_t h[8], l[8];
#pragma unroll
    for (int i = 0; i < 8; i++) {
        __nv_bfloat16 hb = __float2bfloat16(v[i]);
        float         r  = v[i] - __bfloat162float(hb);
        __nv_bfloat16 lb = __float2bfloat16(r);
        h[i]             = (uint32_t)__bfloat16_as_ushort(hb);
        l[i]             = (uint32_t)__bfloat16_as_ushort(lb);
    }
    hi = make_uint4(h[0] | (h[1] << 16), h[2] | (h[3] << 16), h[4] | (h[5] << 16),
                    h[6] | (h[7] << 16));
    lo = make_uint4(l[0] | (l[1] << 16), l[2] | (l[3] << 16), l[4] | (l[5] << 16),
                    l[6] | (l[7] << 16));
}

// ---------------- atom encoder ----------------
__global__ void atom_enc_kernel(const int* __restrict__ x, const float* __restrict__ emb) {
    int i = blockIdx.x * blockDim.x + threadIdx.x;
    int n = i >> 7;
    int d = i & 127;
    float s = 0.f;
#pragma unroll
    for (int k = 0; k < 9; k++) {
        int v = x[n * 9 + k];
        s += emb[((size_t)(k * 128 + v)) * 128 + d];
    }
    g_h[i] = s;
}

__global__ void init_z_kernel(const float* __restrict__ eps_l) {
    int i = blockIdx.x * blockDim.x + threadIdx.x;
    g_z[i] = (1.f + eps_l[0]) * g_h[i];
}

// ---------------- per-layer weight prep: transpose + bf16 split ----------------
// W1 [k=128][n=256] -> g_w1h/l [n][k]; W2 [k=256][n=128] -> g_w2h/l [n][k]
__global__ void wprep_kernel(const float* __restrict__ W1, const float* __restrict__ W2) {
    int i = blockIdx.x * blockDim.x + threadIdx.x;  // 0 .. 65535
    if (i < 32768) {
        int   k = i >> 8;
        int   n = i & 255;
        float w = W1[i];
        __nv_bfloat16 hb = __float2bfloat16(w);
        __nv_bfloat16 lb = __float2bfloat16(w - __bfloat162float(hb));
        g_w1h[n * DD + k] = hb;
        g_w1l[n * DD + k] = lb;
    } else {
        int   j = i - 32768;
        int   k = j >> 7;
        int   n = j & 127;
        float w = W2[j];
        __nv_bfloat16 hb = __float2bfloat16(w);
        __nv_bfloat16 lb = __float2bfloat16(w - __bfloat162float(hb));
        g_w2h[n * D2 + k] = hb;
        g_w2l[n * D2 + k] = lb;
    }
}

// ---------------- edge scatter ----------------
__global__ void scatter_kernel(const int* __restrict__ ei, const int* __restrict__ ea,
                               const float* __restrict__ be) {
    int gw   = (blockIdx.x * blockDim.x + threadIdx.x) >> 5;
    int lane = threadIdx.x & 31;
    if (gw >= NE) return;
    int src = ei[gw];
    int dst = ei[NE + gw];
    int a0 = ea[gw * 3 + 0];
    int a1 = ea[gw * 3 + 1];
    int a2 = ea[gw * 3 + 2];
    float4 e0 = ((const float4*)(be + (0 * 8 + a0) * DD))[lane];
    float4 e1 = ((const float4*)(be + (1 * 8 + a1) * DD))[lane];
    float4 e2 = ((const float4*)(be + (2 * 8 + a2) * DD))[lane];
    float4 hv = ((const float4*)(g_h + (size_t)src * DD))[lane];
    float4 m;
    m.x = fmaxf(hv.x + e0.x + e1.x + e2.x, 0.f);
    m.y = fmaxf(hv.y + e0.y + e1.y + e2.y, 0.f);
    m.z = fmaxf(hv.z + e0.z + e1.z + e2.z, 0.f);
    m.w = fmaxf(hv.w + e0.w + e1.w + e2.w, 0.f);
    atomicAdd((float4*)(g_z + (size_t)dst * DD + lane * 4), m);
}

// =================================================================================
// GEMM1 (HMMA): y = z @ W1 + b1.  M-tile 128, N=256, K=128. 16 warps, warp tile 32x64.
// smem: A_hi/A_lo [128][136] bf16, B_hi/B_lo [256][136] bf16  (208896 B)
// =================================================================================
#define SA1 136
#define G1_ALO 34816
#define G1_BHI 69632
#define G1_BLO 139264
#define G1_SMEM 208896

__global__ void __launch_bounds__(512, 1)
gemm1_tc(const float* __restrict__ bias) {
    extern __shared__ char sm[];
    __nv_bfloat16* sAh = (__nv_bfloat16*)sm;
    __nv_bfloat16* sAl = (__nv_bfloat16*)(sm + G1_ALO);
    __nv_bfloat16* sBh = (__nv_bfloat16*)(sm + G1_BHI);
    __nv_bfloat16* sBl = (__nv_bfloat16*)(sm + G1_BLO);

    const int t    = threadIdx.x;
    const int lane = t & 31;
    const int wid  = t >> 5;
    const int row0 = blockIdx.x * 128;
    const int gid  = lane >> 2;
    const int q    = lane & 3;

    // --- stage A: z[row0..row0+127][0..127] -> bf16 hi/lo ---
    {
        int          r     = t >> 2;
        int          qq    = t & 3;
        const float* rp    = g_z + (size_t)(row0 + r) * DD;
        bool         valid = (row0 + r) < NN;
#pragma unroll
        for (int j = 0; j < 4; j++) {
            int   k0 = qq * 32 + j * 8;
            float v[8];
            if (valid) {
                float4 a = ((const float4*)rp)[k0 >> 2];
                float4 b = ((const float4*)rp)[(k0 >> 2) + 1];
                v[0] = a.x; v[1] = a.y; v[2] = a.z; v[3] = a.w;
                v[4] = b.x; v[5] = b.y; v[6] = b.z; v[7] = b.w;
            } else {
#pragma unroll
                for (int i = 0; i < 8; i++) v[i] = 0.f;
            }
            uint4 hi, lo;
            split8(v, hi, lo);
            *(uint4*)(sAh + r * SA1 + k0) = hi;
            *(uint4*)(sAl + r * SA1 + k0) = lo;
        }
    }
    // --- stage B: g_w1h/l [256][128] ---
#pragma unroll
    for (int i = 0; i < 8; i++) {
        int idx = i * 512 + t;  // 4096 uint4
        int n   = idx >> 4;
        int k0  = (idx & 15) * 8;
        *(uint4*)(sBh + n * SA1 + k0) = *(const uint4*)(g_w1h + n * DD + k0);
        *(uint4*)(sBl + n * SA1 + k0) = *(const uint4*)(g_w1l + n * DD + k0);
    }
    __syncthreads();

    const int wm = wid & 3;   // M quadrant (32 rows)
    const int wn = wid >> 2;  // N quadrant (64 cols)

    float acc[2][8][4];
#pragma unroll
    for (int m = 0; m < 2; m++)
#pragma unroll
        for (int nf = 0; nf < 8; nf++)
#pragma unroll
            for (int j = 0; j < 4; j++) acc[m][nf][j] = 0.f;

#pragma unroll
    for (int ks = 0; ks < 8; ks++) {
        int k0 = ks * 16;
        uint32_t ah[2][4], al[2][4];
#pragma unroll
        for (int m = 0; m < 2; m++) {
            int r = wm * 32 + m * 16 + gid;
            ah[m][0] = *(const uint32_t*)(sAh + r * SA1 + k0 + q * 2);
            ah[m][1] = *(const uint32_t*)(sAh + (r + 8) * SA1 + k0 + q * 2);
            ah[m][2] = *(const uint32_t*)(sAh + r * SA1 + k0 + q * 2 + 8);
            ah[m][3] = *(const uint32_t*)(sAh + (r + 8) * SA1 + k0 + q * 2 + 8);
            al[m][0] = *(const uint32_t*)(sAl + r * SA1 + k0 + q * 2);
            al[m][1] = *(const uint32_t*)(sAl + (r + 8) * SA1 + k0 + q * 2);
            al[m][2] = *(const uint32_t*)(sAl + r * SA1 + k0 + q * 2 + 8);
            al[m][3] = *(const uint32_t*)(sAl + (r + 8) * SA1 + k0 + q * 2 + 8);
        }
#pragma unroll
        for (int nf = 0; nf < 8; nf++) {
            int      n = wn * 64 + nf * 8 + gid;
            uint32_t bh[2], bl[2];
            bh[0] = *(const uint32_t*)(sBh + n * SA1 + k0 + q * 2);
            bh[1] = *(const uint32_t*)(sBh + n * SA1 + k0 + q * 2 + 8);
            bl[0] = *(const uint32_t*)(sBl + n * SA1 + k0 + q * 2);
            bl[1] = *(const uint32_t*)(sBl + n * SA1 + k0 + q * 2 + 8);
#pragma unroll
            for (int m = 0; m < 2; m++) {
                mma16816(acc[m][nf], ah[m], bh);
                mma16816(acc[m][nf], ah[m], bl);
                mma16816(acc[m][nf], al[m], bh);
            }
        }
    }

    // --- epilogue ---
#pragma unroll
    for (int m = 0; m < 2; m++) {
        int r = row0 + wm * 32 + m * 16 + gid;
#pragma unroll
        for (int nf = 0; nf < 8; nf++) {
            int    c  = wn * 64 + nf * 8 + q * 2;
            float2 b2 = *(const float2*)(bias + c);
            if (r < NN) {
                float2 o0 = make_float2(acc[m][nf][0] + b2.x, acc[m][nf][1] + b2.y);
                *(float2*)(g_y + (size_t)r * D2 + c) = o0;
            }
            if (r + 8 < NN) {
                float2 o1 = make_float2(acc[m][nf][2] + b2.x, acc[m][nf][3] + b2.y);
                *(float2*)(g_y + (size_t)(r + 8) * D2 + c) = o1;
            }
        }
    }
}

// =================================================================================
// GEMM2 (HMMA): z2 = relu(bn1(y)) @ W2 + b2.  M-tile 128, N=128, K=256.
// 16 warps, warp tile 32x32. Two B phases (hi, then lo) reusing one B buffer.
// smem: A_hi/A_lo [128][264] bf16 (67584 each), B [128][264] bf16 (67584) = 202752 B
// =================================================================================
#define SA2 264
#define G2_ALO 67584
#define G2_B 135168
#define G2_SMEM 202752

__global__ void __launch_bounds__(512, 1)
gemm2_tc(const float* __restrict__ bias) {
    extern __shared__ char sm[];
    __nv_bfloat16* sAh = (__nv_bfloat16*)sm;
    __nv_bfloat16* sAl = (__nv_bfloat16*)(sm + G2_ALO);
    __nv_bfloat16* sB  = (__nv_bfloat16*)(sm + G2_B);

    const int t    = threadIdx.x;
    const int lane = t & 31;
    const int wid  = t >> 5;
    const int row0 = blockIdx.x * 128;
    const int gid  = lane >> 2;
    const int q    = lane & 3;

    // --- stage A = relu(bn1(y)) ---
    {
        int          r     = t >> 2;
        int          qq    = t & 3;
        const float* rp    = g_y + (size_t)(row0 + r) * D2;
        bool         valid = (row0 + r) < NN;
#pragma unroll
        for (int j = 0; j < 8; j++) {
            int   k0 = qq * 64 + j * 8;
            float v[8];
            if (valid) {
                float4 a = ((const float4*)rp)[k0 >> 2];
                float4 b = ((const float4*)rp)[(k0 >> 2) + 1];
                float  raw[8] = {a.x, a.y, a.z, a.w, b.x, b.y, b.z, b.w};
#pragma unroll
                for (int i = 0; i < 8; i++)
                    v[i] = fmaxf(raw[i] * g_sc[k0 + i] + g_sh[k0 + i], 0.f);
            } else {
#pragma unroll
                for (int i = 0; i < 8; i++) v[i] = 0.f;
            }
            uint4 hi, lo;
            split8(v, hi, lo);
            *(uint4*)(sAh + r * SA2 + k0) = hi;
            *(uint4*)(sAl + r * SA2 + k0) = lo;
        }
    }
    // --- stage B = W2hi^T [128][256] ---
#pragma unroll
    for (int i = 0; i < 8; i++) {
        int idx = i * 512 + t;  // 4096 uint4
        int n   = idx >> 5;
        int k0  = (idx & 31) * 8;
        *(uint4*)(sB + n * SA2 + k0) = *(const uint4*)(g_w2h + n * D2 + k0);
    }
    __syncthreads();

    const int wm = wid & 3;
    const int wn = wid >> 2;  // N quadrant (32 cols)

    float acc[2][4][4];
#pragma unroll
    for (int m = 0; m < 2; m++)
#pragma unroll
        for (int nf = 0; nf < 4; nf++)
#pragma unroll
            for (int j = 0; j < 4; j++) acc[m][nf][j] = 0.f;

    // phase 1: Ahi*Bhi + Alo*Bhi
#pragma unroll
    for (int ks = 0; ks < 16; ks++) {
        int k0 = ks * 16;
        uint32_t ah[2][4], al[2][4];
#pragma unroll
        for (int m = 0; m < 2; m++) {
            int r = wm * 32 + m * 16 + gid;
            ah[m][0] = *(const uint32_t*)(sAh + r * SA2 + k0 + q * 2);
            ah[m][1] = *(const uint32_t*)(sAh + (r + 8) * SA2 + k0 + q * 2);
            ah[m][2] = *(const uint32_t*)(sAh + r * SA2 + k0 + q * 2 + 8);
            ah[m][3] = *(const uint32_t*)(sAh + (r + 8) * SA2 + k0 + q * 2 + 8);
            al[m][0] = *(const uint32_t*)(sAl + r * SA2 + k0 + q * 2);
            al[m][1] = *(const uint32_t*)(sAl + (r + 8) * SA2 + k0 + q * 2);
            al[m][2] = *(const uint32_t*)(sAl + r * SA2 + k0 + q * 2 + 8);
            al[m][3] = *(const uint32_t*)(sAl + (r + 8) * SA2 + k0 + q * 2 + 8);
        }
#pragma unroll
        for (int nf = 0; nf < 4; nf++) {
            int      n = wn * 32 + nf * 8 + gid;
            uint32_t bh[2];
            bh[0] = *(const uint32_t*)(sB + n * SA2 + k0 + q * 2);
            bh[1] = *(const uint32_t*)(sB + n * SA2 + k0 + q * 2 + 8);
#pragma unroll
            for (int m = 0; m < 2; m++) {
                mma16816(acc[m][nf], ah[m], bh);
                mma16816(acc[m][nf], al[m], bh);
            }
        }
    }

    __syncthreads();
    // restage B = W2lo^T
#pragma unroll
    for (int i = 0; i < 8; i++) {
        int idx = i * 512 + t;
        int n   = idx >> 5;
        int k0  = (idx & 31) * 8;
        *(uint4*)(sB + n * SA2 + k0) = *(const uint4*)(g_w2l + n * D2 + k0);
    }
    __syncthreads();

    // phase 2: Ahi*Blo
#pragma unroll
    for (int ks = 0; ks < 16; ks++) {
        int k0 = ks * 16;
        uint32_t ah[2][4];
#pragma unroll
        for (int m = 0; m < 2; m++) {
            int r = wm * 32 + m * 16 + gid;
            ah[m][0] = *(const uint32_t*)(sAh + r * SA2 + k0 + q * 2);
            ah[m][1] = *(const uint32_t*)(sAh + (r + 8) * SA2 + k0 + q * 2);
            ah[m][2] = *(const uint32_t*)(sAh + r * SA2 + k0 + q * 2 + 8);
            ah[m][3] = *(const uint32_t*)(sAh + (r + 8) * SA2 + k0 + q * 2 + 8);
        }
#pragma unroll
        for (int nf = 0; nf < 4; nf++) {
            int      n = wn * 32 + nf * 8 + gid;
            uint32_t bl[2];
            bl[0] = *(const uint32_t*)(sB + n * SA2 + k0 + q * 2);
            bl[1] = *(const uint32_t*)(sB + n * SA2 + k0 + q * 2 + 8);
#pragma unroll
            for (int m = 0; m < 2; m++) mma16816(acc[m][nf], ah[m], bl);
        }
    }

    // --- epilogue -> g_z ---
#pragma unroll
    for (int m = 0; m < 2; m++) {
        int r = row0 + wm * 32 + m * 16 + gid;
#pragma unroll
        for (int nf = 0; nf < 4; nf++) {
            int    c  = wn * 32 + nf * 8 + q * 2;
            float2 b2 = *(const float2*)(bias + c);
            if (r < NN) {
                float2 o0 = make_float2(acc[m][nf][0] + b2.x, acc[m][nf][1] + b2.y);
                *(float2*)(g_z + (size_t)r * DD + c) = o0;
            }
            if (r + 8 < NN) {
                float2 o1 = make_float2(acc[m][nf][2] + b2.x, acc[m][nf][3] + b2.y);
                *(float2*)(g_z + (size_t)(r + 8) * DD + c) = o1;
            }
        }
    }
}

// ---------------- column stats ----------------
__global__ void zero_stats_kernel() { g_stats[threadIdx.x] = 0.f; }

__global__ void colstats_y_kernel() {
    int   c  = threadIdx.x;
    int   r0 = blockIdx.x * 128;
    float s = 0.f, qq = 0.f;
    for (int i = 0; i < 128; i++) {
        int r = r0 + i;
        if (r < NN) {
            float v = g_y[(size_t)r * D2 + c];
            s += v;
            qq += v * v;
        }
    }
    atomicAdd(&g_stats[c], s);
    atomicAdd(&g_stats[256 + c], qq);
}

__global__ void colstats_z_kernel() {
    int   c  = threadIdx.x;
    int   r0 = blockIdx.x * 128;
    float s = 0.f, qq = 0.f;
    for (int i = 0; i < 128; i++) {
        int r = r0 + i;
        if (r < NN) {
            float v = g_z[(size_t)r * DD + c];
            s += v;
            qq += v * v;
        }
    }
    atomicAdd(&g_stats[c], s);
    atomicAdd(&g_stats[256 + c], qq);
}

__global__ void finalize_kernel(const float* __restrict__ g, const float* __restrict__ be,
                                int ncols) {
    int c = threadIdx.x;
    if (c < ncols) {
        float mu   = g_stats[c] * (1.f / NN);
        float var  = g_stats[256 + c] * (1.f / NN) - mu * mu;
        float istd = rsqrtf(var + 1e-5f);
        float s    = g[c] * istd;
        g_sc[c]    = s;
        g_sh[c]    = be[c] - mu * s;
    }
}

__global__ void norm_out_kernel(float* __restrict__ out, int is_last) {
    int   i = blockIdx.x * blockDim.x + threadIdx.x;
    int   c = i & (DD - 1);
    float v = g_z[i] * g_sc[c] + g_sh[c];
    if (is_last) {
        out[i] = v;
    } else {
        g_h[i] = fmaxf(v, 0.f);
    }
}

// ---------------- launch ----------------
extern "C" void kernel_launch(void* const* d_in, const int* in_sizes, int n_in,
                              void* d_out, int out_size) {
    const int*   x    = (const int*)d_in[0];
    const int*   ei   = (const int*)d_in[1];
    const int*   ea   = (const int*)d_in[2];
    const float* aemb = (const float*)d_in[3];
    const float* bemb = (const float*)d_in[4];
    const float* W1   = (const float*)d_in[5];
    const float* b1   = (const float*)d_in[6];
    const float* g1   = (const float*)d_in[7];
    const float* be1  = (const float*)d_in[8];
    const float* W2   = (const float*)d_in[9];
    const float* b2   = (const float*)d_in[10];
    const float* eps  = (const float*)d_in[11];
    const float* gout = (const float*)d_in[12];
    const float* beo  = (const float*)d_in[13];
    float*       out  = (float*)d_out;

    cudaFuncSetAttribute(gemm1_tc, cudaFuncAttributeMaxDynamicSharedMemorySize, G1_SMEM);
    cudaFuncSetAttribute(gemm2_tc, cudaFuncAttributeMaxDynamicSharedMemorySize, G2_SMEM);

    atom_enc_kernel<<<(NN * DD) / 256, 256>>>(x, aemb);

    const int mblocks = (NN + 127) / 128;
    for (int l = 0; l < NL; l++) {
        wprep_kernel<<<128, 512>>>(W1 + (size_t)l * DD * D2, W2 + (size_t)l * D2 * DD);
        init_z_kernel<<<(NN * DD) / 256, 256>>>(eps + l);
        scatter_kernel<<<NE / 8, 256>>>(ei, ea, bemb + l * 3 * 8 * DD);

        gemm1_tc<<<mblocks, 512, G1_SMEM>>>(b1 + l * D2);
        zero_stats_kernel<<<1, 512>>>();
        colstats_y_kernel<<<mblocks, 256>>>();
        finalize_kernel<<<1, 256>>>(g1 + l * D2, be1 + l * D2, D2);

        gemm2_tc<<<mblocks, 512, G2_SMEM>>>(b2 + l * DD);
        zero_stats_kernel<<<1, 512>>>();
        colstats_z_kernel<<<mblocks, 128>>>();
        finalize_kernel<<<1, 256>>>(gout + l * DD, beo + l * DD, DD);

        norm_out_kernel<<<(NN * DD) / 256, 256>>>(out, (l == NL - 1) ? 1 : 0);
    }
}

// round 5
// speedup vs baseline: 1.4903x; 1.1029x over previous
#include <cuda_runtime.h>
#include <cuda_bf16.h>
#include <cstdint>

#define NN 50000
#define DD 128
#define D2 256
#define NE 600000
#define NL 5

// ---------------- device scratch ----------------
__device__ __align__(16) float g_h[NN * DD];
__device__ __align__(16) float g_z[NN * DD];
__device__ __align__(16) float g_y[NN * D2];
__device__ float g_stats[2 * D2];
__device__ float g_sc[D2];
__device__ float g_sh[D2];
// weights (per-layer, transposed, bf16 hi/lo)
__device__ __align__(16) __nv_bfloat16 g_w1h[D2 * DD];
__device__ __align__(16) __nv_bfloat16 g_w1l[D2 * DD];
__device__ __align__(16) __nv_bfloat16 g_w2h[DD * D2];
__device__ __align__(16) __nv_bfloat16 g_w2l[DD * D2];
// CSR (built once per launch)
__device__ int g_cnt[NN];     // degree (kept)
__device__ int g_cnt2[NN];    // fill cursors
__device__ int g_scan[NN];    // block-local inclusive scan
__device__ int g_bsum[128];   // block sums
__device__ int g_boff[128];   // block offsets (exclusive)
__device__ int g_rowptr[NN];  // exclusive start
__device__ int g_csrc[NE];    // src node per CSR slot
__device__ int g_ca[NE];      // packed edge attrs (4 bits each)

// ---------------- mma.sync wrapper (m16n8k16, bf16 x bf16 -> f32) ----------------
__device__ __forceinline__ void mma16816(float* c, const uint32_t* a, const uint32_t* b) {
    asm volatile(
        "mma.sync.aligned.m16n8k16.row.col.f32.bf16.bf16.f32 "
        "{%0,%1,%2,%3}, {%4,%5,%6,%7}, {%8,%9}, {%0,%1,%2,%3};"
        : "+f"(c[0]), "+f"(c[1]), "+f"(c[2]), "+f"(c[3])
        : "r"(a[0]), "r"(a[1]), "r"(a[2]), "r"(a[3]), "r"(b[0]), "r"(b[1]));
}

__device__ __forceinline__ void split8(const float* v, uint4& hi, uint4& lo) {
    uint32_t h[8], l[8];
#pragma unroll
    for (int i = 0; i < 8; i++) {
        __nv_bfloat16 hb = __float2bfloat16(v[i]);
        float         r  = v[i] - __bfloat162float(hb);
        __nv_bfloat16 lb = __float2bfloat16(r);
        h[i]             = (uint32_t)__bfloat16_as_ushort(hb);
        l[i]             = (uint32_t)__bfloat16_as_ushort(lb);
    }
    hi = make_uint4(h[0] | (h[1] << 16), h[2] | (h[3] << 16), h[4] | (h[5] << 16),
                    h[6] | (h[7] << 16));
    lo = make_uint4(l[0] | (l[1] << 16), l[2] | (l[3] << 16), l[4] | (l[5] << 16),
                    l[6] | (l[7] << 16));
}

// ---------------- atom encoder ----------------
__global__ void atom_enc_kernel(const int* __restrict__ x, const float* __restrict__ emb) {
    int i = blockIdx.x * blockDim.x + threadIdx.x;
    int n = i >> 7;
    int d = i & 127;
    float s = 0.f;
#pragma unroll
    for (int k = 0; k < 9; k++) {
        int v = x[n * 9 + k];
        s += emb[((size_t)(k * 128 + v)) * 128 + d];
    }
    g_h[i] = s;
}

// ---------------- CSR build ----------------
__global__ void zero_cnt_kernel() {
    int i = blockIdx.x * blockDim.x + threadIdx.x;
    if (i < NN) g_cnt[i] = 0;
}
__global__ void hist_kernel(const int* __restrict__ ei) {
    int e = blockIdx.x * blockDim.x + threadIdx.x;
    if (e < NE) atomicAdd(&g_cnt[ei[NE + e]], 1);
}
__global__ void scan1_kernel() {  // 98 blocks x 512
    __shared__ int sh[512];
    int i          = blockIdx.x * 512 + threadIdx.x;
    int v          = (i < NN) ? g_cnt[i] : 0;
    sh[threadIdx.x] = v;
    __syncthreads();
#pragma unroll
    for (int o = 1; o < 512; o <<= 1) {
        int t = (threadIdx.x >= o) ? sh[threadIdx.x - o] : 0;
        __syncthreads();
        sh[threadIdx.x] += t;
        __syncthreads();
    }
    if (i < NN) g_scan[i] = sh[threadIdx.x];
    if (threadIdx.x == 511) g_bsum[blockIdx.x] = sh[511];
}
__global__ void scan2_kernel(int nb) {
    if (threadIdx.x == 0) {
        int run = 0;
        for (int b = 0; b < nb; b++) {
            g_boff[b] = run;
            run += g_bsum[b];
        }
    }
}
__global__ void scan3_kernel() {
    int i = blockIdx.x * blockDim.x + threadIdx.x;
    if (i < NN) {
        g_rowptr[i] = g_scan[i] - g_cnt[i] + g_boff[i >> 9];
        g_cnt2[i]   = 0;
    }
}
__global__ void fill_kernel(const int* __restrict__ ei, const int* __restrict__ ea) {
    int e = blockIdx.x * blockDim.x + threadIdx.x;
    if (e >= NE) return;
    int dst     = ei[NE + e];
    int slot    = atomicAdd(&g_cnt2[dst], 1);
    int idx     = g_rowptr[dst] + slot;
    g_csrc[idx] = ei[e];
    g_ca[idx]   = ea[e * 3] | (ea[e * 3 + 1] << 4) | (ea[e * 3 + 2] << 8);
}

// ---------------- weight prep ----------------
__global__ void wprep_kernel(const float* __restrict__ W1, const float* __restrict__ W2) {
    int i = blockIdx.x * blockDim.x + threadIdx.x;
    if (i < 32768) {
        int   k = i >> 8;
        int   n = i & 255;
        float w = W1[i];
        __nv_bfloat16 hb  = __float2bfloat16(w);
        __nv_bfloat16 lb  = __float2bfloat16(w - __bfloat162float(hb));
        g_w1h[n * DD + k] = hb;
        g_w1l[n * DD + k] = lb;
    } else {
        int   j = i - 32768;
        int   k = j >> 7;
        int   n = j & 127;
        float w = W2[j];
        __nv_bfloat16 hb  = __float2bfloat16(w);
        __nv_bfloat16 lb  = __float2bfloat16(w - __bfloat162float(hb));
        g_w2h[n * D2 + k] = hb;
        g_w2l[n * D2 + k] = lb;
    }
}

// ---------------- fused gather: z = (1+eps)h[dst] + sum relu(h[src]+ee) ----------------
// 256 threads = 8 warps = 8 nodes/block; bond table (12KB) staged in smem.
__global__ void __launch_bounds__(256)
gather_kernel(const float* __restrict__ bemb_l, const float* __restrict__ eps_l) {
    __shared__ float sbond[3 * 8 * DD];
    int t = threadIdx.x;
#pragma unroll
    for (int i = 0; i < 3; i++) ((float4*)sbond)[i * 256 + t] = ((const float4*)bemb_l)[i * 256 + t];
    __syncthreads();

    int node = blockIdx.x * 8 + (t >> 5);
    int lane = t & 31;
    float  ep  = 1.f + eps_l[0];
    float4 acc = ((const float4*)(g_h + (size_t)node * DD))[lane];
    acc.x *= ep;
    acc.y *= ep;
    acc.z *= ep;
    acc.w *= ep;
    int start = g_rowptr[node];
    int deg   = g_cnt[node];
    for (int j = 0; j < deg; j++) {
        int    s  = g_csrc[start + j];
        int    a  = g_ca[start + j];
        float4 hv = ((const float4*)(g_h + (size_t)s * DD))[lane];
        float4 e0 = ((const float4*)(sbond + (a & 15) * DD))[lane];
        float4 e1 = ((const float4*)(sbond + (8 + ((a >> 4) & 15)) * DD))[lane];
        float4 e2 = ((const float4*)(sbond + (16 + ((a >> 8) & 15)) * DD))[lane];
        acc.x += fmaxf(hv.x + e0.x + e1.x + e2.x, 0.f);
        acc.y += fmaxf(hv.y + e0.y + e1.y + e2.y, 0.f);
        acc.z += fmaxf(hv.z + e0.z + e1.z + e2.z, 0.f);
        acc.w += fmaxf(hv.w + e0.w + e1.w + e2.w, 0.f);
    }
    ((float4*)(g_z + (size_t)node * DD))[lane] = acc;
}

// =================================================================================
// GEMM1 (HMMA): y = z @ W1 + b1, fused column stats.  M-tile 128, N=256, K=128.
// =================================================================================
#define SA1 136
#define G1_ALO 34816
#define G1_BHI 69632
#define G1_BLO 139264
#define G1_SMEM 208896

__global__ void __launch_bounds__(512, 1)
gemm1_tc(const float* __restrict__ bias) {
    extern __shared__ char sm[];
    __nv_bfloat16* sAh = (__nv_bfloat16*)sm;
    __nv_bfloat16* sAl = (__nv_bfloat16*)(sm + G1_ALO);
    __nv_bfloat16* sBh = (__nv_bfloat16*)(sm + G1_BHI);
    __nv_bfloat16* sBl = (__nv_bfloat16*)(sm + G1_BLO);

    const int t    = threadIdx.x;
    const int lane = t & 31;
    const int wid  = t >> 5;
    const int row0 = blockIdx.x * 128;
    const int gid  = lane >> 2;
    const int q    = lane & 3;

    {
        int          r     = t >> 2;
        int          qq    = t & 3;
        const float* rp    = g_z + (size_t)(row0 + r) * DD;
        bool         valid = (row0 + r) < NN;
#pragma unroll
        for (int j = 0; j < 4; j++) {
            int   k0 = qq * 32 + j * 8;
            float v[8];
            if (valid) {
                float4 a = ((const float4*)rp)[k0 >> 2];
                float4 b = ((const float4*)rp)[(k0 >> 2) + 1];
                v[0] = a.x; v[1] = a.y; v[2] = a.z; v[3] = a.w;
                v[4] = b.x; v[5] = b.y; v[6] = b.z; v[7] = b.w;
            } else {
#pragma unroll
                for (int i = 0; i < 8; i++) v[i] = 0.f;
            }
            uint4 hi, lo;
            split8(v, hi, lo);
            *(uint4*)(sAh + r * SA1 + k0) = hi;
            *(uint4*)(sAl + r * SA1 + k0) = lo;
        }
    }
#pragma unroll
    for (int i = 0; i < 8; i++) {
        int idx = i * 512 + t;
        int n   = idx >> 4;
        int k0  = (idx & 15) * 8;
        *(uint4*)(sBh + n * SA1 + k0) = *(const uint4*)(g_w1h + n * DD + k0);
        *(uint4*)(sBl + n * SA1 + k0) = *(const uint4*)(g_w1l + n * DD + k0);
    }
    __syncthreads();

    const int wm = wid & 3;
    const int wn = wid >> 2;

    float acc[2][8][4];
#pragma unroll
    for (int m = 0; m < 2; m++)
#pragma unroll
        for (int nf = 0; nf < 8; nf++)
#pragma unroll
            for (int j = 0; j < 4; j++) acc[m][nf][j] = 0.f;

#pragma unroll
    for (int ks = 0; ks < 8; ks++) {
        int k0 = ks * 16;
        uint32_t ah[2][4], al[2][4];
#pragma unroll
        for (int m = 0; m < 2; m++) {
            int r = wm * 32 + m * 16 + gid;
            ah[m][0] = *(const uint32_t*)(sAh + r * SA1 + k0 + q * 2);
            ah[m][1] = *(const uint32_t*)(sAh + (r + 8) * SA1 + k0 + q * 2);
            ah[m][2] = *(const uint32_t*)(sAh + r * SA1 + k0 + q * 2 + 8);
            ah[m][3] = *(const uint32_t*)(sAh + (r + 8) * SA1 + k0 + q * 2 + 8);
            al[m][0] = *(const uint32_t*)(sAl + r * SA1 + k0 + q * 2);
            al[m][1] = *(const uint32_t*)(sAl + (r + 8) * SA1 + k0 + q * 2);
            al[m][2] = *(const uint32_t*)(sAl + r * SA1 + k0 + q * 2 + 8);
            al[m][3] = *(const uint32_t*)(sAl + (r + 8) * SA1 + k0 + q * 2 + 8);
        }
#pragma unroll
        for (int nf = 0; nf < 8; nf++) {
            int      n = wn * 64 + nf * 8 + gid;
            uint32_t bh[2], bl[2];
            bh[0] = *(const uint32_t*)(sBh + n * SA1 + k0 + q * 2);
            bh[1] = *(const uint32_t*)(sBh + n * SA1 + k0 + q * 2 + 8);
            bl[0] = *(const uint32_t*)(sBl + n * SA1 + k0 + q * 2);
            bl[1] = *(const uint32_t*)(sBl + n * SA1 + k0 + q * 2 + 8);
#pragma unroll
            for (int m = 0; m < 2; m++) {
                mma16816(acc[m][nf], ah[m], bh);
                mma16816(acc[m][nf], ah[m], bl);
                mma16816(acc[m][nf], al[m], bh);
            }
        }
    }

    // epilogue + fused column stats
#pragma unroll
    for (int nf = 0; nf < 8; nf++) {
        int    c  = wn * 64 + nf * 8 + q * 2;
        float2 b2 = *(const float2*)(bias + c);
        float  sx = 0.f, sy = 0.f, qx = 0.f, qy = 0.f;
#pragma unroll
        for (int m = 0; m < 2; m++) {
            int r = row0 + wm * 32 + m * 16 + gid;
            if (r < NN) {
                float vx = acc[m][nf][0] + b2.x;
                float vy = acc[m][nf][1] + b2.y;
                *(float2*)(g_y + (size_t)r * D2 + c) = make_float2(vx, vy);
                sx += vx; sy += vy; qx += vx * vx; qy += vy * vy;
            }
            if (r + 8 < NN) {
                float vx = acc[m][nf][2] + b2.x;
                float vy = acc[m][nf][3] + b2.y;
                *(float2*)(g_y + (size_t)(r + 8) * D2 + c) = make_float2(vx, vy);
                sx += vx; sy += vy; qx += vx * vx; qy += vy * vy;
            }
        }
#pragma unroll
        for (int o = 4; o < 32; o <<= 1) {
            sx += __shfl_xor_sync(0xffffffff, sx, o);
            sy += __shfl_xor_sync(0xffffffff, sy, o);
            qx += __shfl_xor_sync(0xffffffff, qx, o);
            qy += __shfl_xor_sync(0xffffffff, qy, o);
        }
        if (gid == 0) {
            atomicAdd(&g_stats[c], sx);
            atomicAdd(&g_stats[c + 1], sy);
            atomicAdd(&g_stats[256 + c], qx);
            atomicAdd(&g_stats[256 + c + 1], qy);
        }
    }
}

// =================================================================================
// GEMM2 (HMMA): z2 = relu(bn1(y)) @ W2 + b2, fused column stats. N=128, K=256.
// =================================================================================
#define SA2 264
#define G2_ALO 67584
#define G2_B 135168
#define G2_SMEM 202752

__global__ void __launch_bounds__(512, 1)
gemm2_tc(const float* __restrict__ bias) {
    extern __shared__ char sm[];
    __nv_bfloat16* sAh = (__nv_bfloat16*)sm;
    __nv_bfloat16* sAl = (__nv_bfloat16*)(sm + G2_ALO);
    __nv_bfloat16* sB  = (__nv_bfloat16*)(sm + G2_B);

    const int t    = threadIdx.x;
    const int lane = t & 31;
    const int wid  = t >> 5;
    const int row0 = blockIdx.x * 128;
    const int gid  = lane >> 2;
    const int q    = lane & 3;

    {
        int          r     = t >> 2;
        int          qq    = t & 3;
        const float* rp    = g_y + (size_t)(row0 + r) * D2;
        bool         valid = (row0 + r) < NN;
#pragma unroll
        for (int j = 0; j < 8; j++) {
            int   k0 = qq * 64 + j * 8;
            float v[8];
            if (valid) {
                float4 a = ((const float4*)rp)[k0 >> 2];
                float4 b = ((const float4*)rp)[(k0 >> 2) + 1];
                float  raw[8] = {a.x, a.y, a.z, a.w, b.x, b.y, b.z, b.w};
#pragma unroll
                for (int i = 0; i < 8; i++)
                    v[i] = fmaxf(raw[i] * g_sc[k0 + i] + g_sh[k0 + i], 0.f);
            } else {
#pragma unroll
                for (int i = 0; i < 8; i++) v[i] = 0.f;
            }
            uint4 hi, lo;
            split8(v, hi, lo);
            *(uint4*)(sAh + r * SA2 + k0) = hi;
            *(uint4*)(sAl + r * SA2 + k0) = lo;
        }
    }
#pragma unroll
    for (int i = 0; i < 8; i++) {
        int idx = i * 512 + t;
        int n   = idx >> 5;
        int k0  = (idx & 31) * 8;
        *(uint4*)(sB + n * SA2 + k0) = *(const uint4*)(g_w2h + n * D2 + k0);
    }
    __syncthreads();

    const int wm = wid & 3;
    const int wn = wid >> 2;

    float acc[2][4][4];
#pragma unroll
    for (int m = 0; m < 2; m++)
#pragma unroll
        for (int nf = 0; nf < 4; nf++)
#pragma unroll
            for (int j = 0; j < 4; j++) acc[m][nf][j] = 0.f;

#pragma unroll
    for (int ks = 0; ks < 16; ks++) {
        int k0 = ks * 16;
        uint32_t ah[2][4], al[2][4];
#pragma unroll
        for (int m = 0; m < 2; m++) {
            int r = wm * 32 + m * 16 + gid;
            ah[m][0] = *(const uint32_t*)(sAh + r * SA2 + k0 + q * 2);
            ah[m][1] = *(const uint32_t*)(sAh + (r + 8) * SA2 + k0 + q * 2);
            ah[m][2] = *(const uint32_t*)(sAh + r * SA2 + k0 + q * 2 + 8);
            ah[m][3] = *(const uint32_t*)(sAh + (r + 8) * SA2 + k0 + q * 2 + 8);
            al[m][0] = *(const uint32_t*)(sAl + r * SA2 + k0 + q * 2);
            al[m][1] = *(const uint32_t*)(sAl + (r + 8) * SA2 + k0 + q * 2);
            al[m][2] = *(const uint32_t*)(sAl + r * SA2 + k0 + q * 2 + 8);
            al[m][3] = *(const uint32_t*)(sAl + (r + 8) * SA2 + k0 + q * 2 + 8);
        }
#pragma unroll
        for (int nf = 0; nf < 4; nf++) {
            int      n = wn * 32 + nf * 8 + gid;
            uint32_t bh[2];
            bh[0] = *(const uint32_t*)(sB + n * SA2 + k0 + q * 2);
            bh[1] = *(const uint32_t*)(sB + n * SA2 + k0 + q * 2 + 8);
#pragma unroll
            for (int m = 0; m < 2; m++) {
                mma16816(acc[m][nf], ah[m], bh);
                mma16816(acc[m][nf], al[m], bh);
            }
        }
    }

    __syncthreads();
#pragma unroll
    for (int i = 0; i < 8; i++) {
        int idx = i * 512 + t;
        int n   = idx >> 5;
        int k0  = (idx & 31) * 8;
        *(uint4*)(sB + n * SA2 + k0) = *(const uint4*)(g_w2l + n * D2 + k0);
    }
    __syncthreads();

#pragma unroll
    for (int ks = 0; ks < 16; ks++) {
        int k0 = ks * 16;
        uint32_t ah[2][4];
#pragma unroll
        for (int m = 0; m < 2; m++) {
            int r = wm * 32 + m * 16 + gid;
            ah[m][0] = *(const uint32_t*)(sAh + r * SA2 + k0 + q * 2);
            ah[m][1] = *(const uint32_t*)(sAh + (r + 8) * SA2 + k0 + q * 2);
            ah[m][2] = *(const uint32_t*)(sAh + r * SA2 + k0 + q * 2 + 8);
            ah[m][3] = *(const uint32_t*)(sAh + (r + 8) * SA2 + k0 + q * 2 + 8);
        }
#pragma unroll
        for (int nf = 0; nf < 4; nf++) {
            int      n = wn * 32 + nf * 8 + gid;
            uint32_t bl[2];
            bl[0] = *(const uint32_t*)(sB + n * SA2 + k0 + q * 2);
            bl[1] = *(const uint32_t*)(sB + n * SA2 + k0 + q * 2 + 8);
#pragma unroll
            for (int m = 0; m < 2; m++) mma16816(acc[m][nf], ah[m], bl);
        }
    }

    // epilogue + fused column stats
#pragma unroll
    for (int nf = 0; nf < 4; nf++) {
        int    c  = wn * 32 + nf * 8 + q * 2;
        float2 b2 = *(const float2*)(bias + c);
        float  sx = 0.f, sy = 0.f, qx = 0.f, qy = 0.f;
#pragma unroll
        for (int m = 0; m < 2; m++) {
            int r = row0 + wm * 32 + m * 16 + gid;
            if (r < NN) {
                float vx = acc[m][nf][0] + b2.x;
                float vy = acc[m][nf][1] + b2.y;
                *(float2*)(g_z + (size_t)r * DD + c) = make_float2(vx, vy);
                sx += vx; sy += vy; qx += vx * vx; qy += vy * vy;
            }
            if (r + 8 < NN) {
                float vx = acc[m][nf][2] + b2.x;
                float vy = acc[m][nf][3] + b2.y;
                *(float2*)(g_z + (size_t)(r + 8) * DD + c) = make_float2(vx, vy);
                sx += vx; sy += vy; qx += vx * vx; qy += vy * vy;
            }
        }
#pragma unroll
        for (int o = 4; o < 32; o <<= 1) {
            sx += __shfl_xor_sync(0xffffffff, sx, o);
            sy += __shfl_xor_sync(0xffffffff, sy, o);
            qx += __shfl_xor_sync(0xffffffff, qx, o);
            qy += __shfl_xor_sync(0xffffffff, qy, o);
        }
        if (gid == 0) {
            atomicAdd(&g_stats[c], sx);
            atomicAdd(&g_stats[c + 1], sy);
            atomicAdd(&g_stats[256 + c], qx);
            atomicAdd(&g_stats[256 + c + 1], qy);
        }
    }
}

// ---------------- stats finalize / norm ----------------
__global__ void zero_stats_kernel() { g_stats[threadIdx.x] = 0.f; }

__global__ void finalize_kernel(const float* __restrict__ g, const float* __restrict__ be,
                                int ncols) {
    int c = threadIdx.x;
    if (c < ncols) {
        float mu   = g_stats[c] * (1.f / NN);
        float var  = g_stats[256 + c] * (1.f / NN) - mu * mu;
        float istd = rsqrtf(var + 1e-5f);
        float s    = g[c] * istd;
        g_sc[c]    = s;
        g_sh[c]    = be[c] - mu * s;
    }
}

__global__ void norm_out_kernel(float* __restrict__ out, int is_last) {
    int   i = blockIdx.x * blockDim.x + threadIdx.x;
    int   c = i & (DD - 1);
    float v = g_z[i] * g_sc[c] + g_sh[c];
    if (is_last) {
        out[i] = v;
    } else {
        g_h[i] = fmaxf(v, 0.f);
    }
}

// ---------------- launch ----------------
extern "C" void kernel_launch(void* const* d_in, const int* in_sizes, int n_in,
                              void* d_out, int out_size) {
    const int*   x    = (const int*)d_in[0];
    const int*   ei   = (const int*)d_in[1];
    const int*   ea   = (const int*)d_in[2];
    const float* aemb = (const float*)d_in[3];
    const float* bemb = (const float*)d_in[4];
    const float* W1   = (const float*)d_in[5];
    const float* b1   = (const float*)d_in[6];
    const float* g1   = (const float*)d_in[7];
    const float* be1  = (const float*)d_in[8];
    const float* W2   = (const float*)d_in[9];
    const float* b2   = (const float*)d_in[10];
    const float* eps  = (const float*)d_in[11];
    const float* gout = (const float*)d_in[12];
    const float* beo  = (const float*)d_in[13];
    float*       out  = (float*)d_out;

    cudaFuncSetAttribute(gemm1_tc, cudaFuncAttributeMaxDynamicSharedMemorySize, G1_SMEM);
    cudaFuncSetAttribute(gemm2_tc, cudaFuncAttributeMaxDynamicSharedMemorySize, G2_SMEM);

    atom_enc_kernel<<<(NN * DD) / 256, 256>>>(x, aemb);

    // CSR build (same inputs every call -> deterministic)
    const int NB = (NN + 511) / 512;  // 98
    zero_cnt_kernel<<<(NN + 255) / 256, 256>>>();
    hist_kernel<<<(NE + 255) / 256, 256>>>(ei);
    scan1_kernel<<<NB, 512>>>();
    scan2_kernel<<<1, 32>>>(NB);
    scan3_kernel<<<(NN + 255) / 256, 256>>>();
    fill_kernel<<<(NE + 255) / 256, 256>>>(ei, ea);

    const int mblocks = (NN + 127) / 128;
    for (int l = 0; l < NL; l++) {
        wprep_kernel<<<128, 512>>>(W1 + (size_t)l * DD * D2, W2 + (size_t)l * D2 * DD);
        gather_kernel<<<NN / 8, 256>>>(bemb + l * 3 * 8 * DD, eps + l);

        zero_stats_kernel<<<1, 512>>>();
        gemm1_tc<<<mblocks, 512, G1_SMEM>>>(b1 + l * D2);
        finalize_kernel<<<1, 256>>>(g1 + l * D2, be1 + l * D2, D2);

        zero_stats_kernel<<<1, 512>>>();
        gemm2_tc<<<mblocks, 512, G2_SMEM>>>(b2 + l * DD);
        finalize_kernel<<<1, 256>>>(gout + l * DD, beo + l * DD, DD);

        norm_out_kernel<<<(NN * DD) / 256, 256>>>(out, (l == NL - 1) ? 1 : 0);
    }
}

// round 7
// speedup vs baseline: 1.5278x; 1.0251x over previous
#include <cuda_runtime.h>
#include <cuda_bf16.h>
#include <cstdint>

#define NN 50000
#define DD 128
#define D2 256
#define NE 600000
#define NL 5

// ---------------- device scratch ----------------
__device__ __align__(16) float g_h[NN * DD];   // atom encoder output (layer-0 input)
__device__ __align__(16) float g_z[NN * DD];   // gather output (gemm1 input)
__device__ __align__(16) float g_y[NN * D2];   // gemm1 output
__device__ __align__(16) float g_v[NN * DD];   // gemm2 output (pre-BN)
__device__ float g_stats[2 * D2];
__device__ float g_sc[D2];
__device__ float g_sh[D2];
// all-layer weight transposes in bf16 hi/lo
__device__ __align__(16) __nv_bfloat16 g_w1h[NL * D2 * DD];
__device__ __align__(16) __nv_bfloat16 g_w1l[NL * D2 * DD];
__device__ __align__(16) __nv_bfloat16 g_w2h[NL * DD * D2];
__device__ __align__(16) __nv_bfloat16 g_w2l[NL * DD * D2];
// CSR
__device__ int g_cnt[NN];
__device__ int g_cnt2[NN];
__device__ int g_scan[NN];
__device__ int g_bsum[128];
__device__ int g_boff[128];
__device__ int g_rowptr[NN];
__device__ int g_csrc[NE];
__device__ int g_ca[NE];

// ---------------- mma.sync wrapper ----------------
__device__ __forceinline__ void mma16816(float* c, const uint32_t* a, const uint32_t* b) {
    asm volatile(
        "mma.sync.aligned.m16n8k16.row.col.f32.bf16.bf16.f32 "
        "{%0,%1,%2,%3}, {%4,%5,%6,%7}, {%8,%9}, {%0,%1,%2,%3};"
        : "+f"(c[0]), "+f"(c[1]), "+f"(c[2]), "+f"(c[3])
        : "r"(a[0]), "r"(a[1]), "r"(a[2]), "r"(a[3]), "r"(b[0]), "r"(b[1]));
}

__device__ __forceinline__ void split8(const float* v, uint4& hi, uint4& lo) {
    uint32_t h[8], l[8];
#pragma unroll
    for (int i = 0; i < 8; i++) {
        __nv_bfloat16 hb = __float2bfloat16(v[i]);
        float         r  = v[i] - __bfloat162float(hb);
        __nv_bfloat16 lb = __float2bfloat16(r);
        h[i]             = (uint32_t)__bfloat16_as_ushort(hb);
        l[i]             = (uint32_t)__bfloat16_as_ushort(lb);
    }
    hi = make_uint4(h[0] | (h[1] << 16), h[2] | (h[3] << 16), h[4] | (h[5] << 16),
                    h[6] | (h[7] << 16));
    lo = make_uint4(l[0] | (l[1] << 16), l[2] | (l[3] << 16), l[4] | (l[5] << 16),
                    l[6] | (l[7] << 16));
}

// ---------------- atom encoder ----------------
__global__ void atom_enc_kernel(const int* __restrict__ x, const float* __restrict__ emb) {
    int i = blockIdx.x * blockDim.x + threadIdx.x;
    int n = i >> 7;
    int d = i & 127;
    float s = 0.f;
#pragma unroll
    for (int k = 0; k < 9; k++) {
        int v = x[n * 9 + k];
        s += emb[((size_t)(k * 128 + v)) * 128 + d];
    }
    g_h[i] = s;
}

// ---------------- CSR build ----------------
__global__ void zero_cnt_kernel() {
    int i = blockIdx.x * blockDim.x + threadIdx.x;
    if (i < NN) g_cnt[i] = 0;
}
__global__ void hist_kernel(const int* __restrict__ ei) {
    int e = blockIdx.x * blockDim.x + threadIdx.x;
    if (e < NE) atomicAdd(&g_cnt[ei[NE + e]], 1);
}
__global__ void scan1_kernel() {
    __shared__ int sh[512];
    int i           = blockIdx.x * 512 + threadIdx.x;
    int v           = (i < NN) ? g_cnt[i] : 0;
    sh[threadIdx.x] = v;
    __syncthreads();
#pragma unroll
    for (int o = 1; o < 512; o <<= 1) {
        int t = (threadIdx.x >= o) ? sh[threadIdx.x - o] : 0;
        __syncthreads();
        sh[threadIdx.x] += t;
        __syncthreads();
    }
    if (i < NN) g_scan[i] = sh[threadIdx.x];
    if (threadIdx.x == 511) g_bsum[blockIdx.x] = sh[511];
}
__global__ void scan2_kernel(int nb) {
    if (threadIdx.x == 0) {
        int run = 0;
        for (int b = 0; b < nb; b++) {
            g_boff[b] = run;
            run += g_bsum[b];
        }
    }
}
__global__ void scan3_kernel() {
    int i = blockIdx.x * blockDim.x + threadIdx.x;
    if (i < NN) {
        g_rowptr[i] = g_scan[i] - g_cnt[i] + g_boff[i >> 9];
        g_cnt2[i]   = 0;
    }
}
__global__ void fill_kernel(const int* __restrict__ ei, const int* __restrict__ ea) {
    int e = blockIdx.x * blockDim.x + threadIdx.x;
    if (e >= NE) return;
    int dst     = ei[NE + e];
    int slot    = atomicAdd(&g_cnt2[dst], 1);
    int idx     = g_rowptr[dst] + slot;
    g_csrc[idx] = ei[e];
    g_ca[idx]   = ea[e * 3] | (ea[e * 3 + 1] << 4) | (ea[e * 3 + 2] << 8);
}

// ---------------- weight prep (all layers at once) ----------------
__global__ void wprep_all_kernel(const float* __restrict__ W1, const float* __restrict__ W2) {
    int i = blockIdx.x * blockDim.x + threadIdx.x;  // 0 .. 5*65536-1
    int l = i >> 16;
    int j = i & 65535;
    if (j < 32768) {
        int   k = j >> 8;
        int   n = j & 255;
        float w = W1[l * 32768 + j];
        __nv_bfloat16 hb = __float2bfloat16(w);
        __nv_bfloat16 lb = __float2bfloat16(w - __bfloat162float(hb));
        g_w1h[l * 32768 + n * DD + k] = hb;
        g_w1l[l * 32768 + n * DD + k] = lb;
    } else {
        int   jj = j - 32768;
        int   k  = jj >> 7;
        int   n  = jj & 127;
        float w  = W2[l * 32768 + jj];
        __nv_bfloat16 hb = __float2bfloat16(w);
        __nv_bfloat16 lb = __float2bfloat16(w - __bfloat162float(hb));
        g_w2h[l * 32768 + n * D2 + k] = hb;
        g_w2l[l * 32768 + n * D2 + k] = lb;
    }
}

// ---------------- fused gather (+BN+relu of source): z = (1+eps)hbn[dst] + sum relu(hbn[src]+ee)
// src array selected INSIDE device code (g_h for layer 0, g_v + BN otherwise).
// 256 threads = 8 warps, each warp handles 8 nodes -> 64 nodes/block.
template <int APPLY_BN>
__global__ void __launch_bounds__(256)
gather_kernel(const float* __restrict__ bemb_l, const float* __restrict__ eps_l) {
    __shared__ float sbond[3 * 8 * DD];
    int t = threadIdx.x;
#pragma unroll
    for (int i = 0; i < 3; i++)
        ((float4*)sbond)[i * 256 + t] = ((const float4*)bemb_l)[i * 256 + t];
    __syncthreads();

    const float* src = APPLY_BN ? g_v : g_h;

    int    wid  = t >> 5;
    int    lane = t & 31;
    float  ep   = 1.f + eps_l[0];
    float4 sc4, sh4;
    if (APPLY_BN) {
        sc4 = ((const float4*)g_sc)[lane];
        sh4 = ((const float4*)g_sh)[lane];
    }

#pragma unroll
    for (int nj = 0; nj < 8; nj++) {
        int node = blockIdx.x * 64 + wid * 8 + nj;
        if (node >= NN) break;
        float4 acc = ((const float4*)(src + (size_t)node * DD))[lane];
        if (APPLY_BN) {
            acc.x = fmaxf(acc.x * sc4.x + sh4.x, 0.f);
            acc.y = fmaxf(acc.y * sc4.y + sh4.y, 0.f);
            acc.z = fmaxf(acc.z * sc4.z + sh4.z, 0.f);
            acc.w = fmaxf(acc.w * sc4.w + sh4.w, 0.f);
        }
        acc.x *= ep;
        acc.y *= ep;
        acc.z *= ep;
        acc.w *= ep;
        int start = g_rowptr[node];
        int deg   = g_cnt[node];
        for (int j = 0; j < deg; j++) {
            int    s  = g_csrc[start + j];
            int    a  = g_ca[start + j];
            float4 hv = ((const float4*)(src + (size_t)s * DD))[lane];
            if (APPLY_BN) {
                hv.x = fmaxf(hv.x * sc4.x + sh4.x, 0.f);
                hv.y = fmaxf(hv.y * sc4.y + sh4.y, 0.f);
                hv.z = fmaxf(hv.z * sc4.z + sh4.z, 0.f);
                hv.w = fmaxf(hv.w * sc4.w + sh4.w, 0.f);
            }
            float4 e0 = ((const float4*)(sbond + (a & 15) * DD))[lane];
            float4 e1 = ((const float4*)(sbond + (8 + ((a >> 4) & 15)) * DD))[lane];
            float4 e2 = ((const float4*)(sbond + (16 + ((a >> 8) & 15)) * DD))[lane];
            acc.x += fmaxf(hv.x + e0.x + e1.x + e2.x, 0.f);
            acc.y += fmaxf(hv.y + e0.y + e1.y + e2.y, 0.f);
            acc.z += fmaxf(hv.z + e0.z + e1.z + e2.z, 0.f);
            acc.w += fmaxf(hv.w + e0.w + e1.w + e2.w, 0.f);
        }
        ((float4*)(g_z + (size_t)node * DD))[lane] = acc;
    }
}

// =================================================================================
// GEMM1 (HMMA): y = z @ W1 + b1, fused column stats.  M-tile 128, N=256, K=128.
// =================================================================================
#define SA1 136
#define G1_ALO 34816
#define G1_BHI 69632
#define G1_BLO 139264
#define G1_SMEM 208896

__global__ void __launch_bounds__(512, 1)
gemm1_tc(const float* __restrict__ bias, int layer) {
    extern __shared__ char sm[];
    __nv_bfloat16* sAh = (__nv_bfloat16*)sm;
    __nv_bfloat16* sAl = (__nv_bfloat16*)(sm + G1_ALO);
    __nv_bfloat16* sBh = (__nv_bfloat16*)(sm + G1_BHI);
    __nv_bfloat16* sBl = (__nv_bfloat16*)(sm + G1_BLO);

    const __nv_bfloat16* wh = g_w1h + layer * 32768;
    const __nv_bfloat16* wl = g_w1l + layer * 32768;

    const int t    = threadIdx.x;
    const int lane = t & 31;
    const int wid  = t >> 5;
    const int row0 = blockIdx.x * 128;
    const int gid  = lane >> 2;
    const int q    = lane & 3;

    {
        int          r     = t >> 2;
        int          qq    = t & 3;
        const float* rp    = g_z + (size_t)(row0 + r) * DD;
        bool         valid = (row0 + r) < NN;
#pragma unroll
        for (int j = 0; j < 4; j++) {
            int   k0 = qq * 32 + j * 8;
            float v[8];
            if (valid) {
                float4 a = ((const float4*)rp)[k0 >> 2];
                float4 b = ((const float4*)rp)[(k0 >> 2) + 1];
                v[0] = a.x; v[1] = a.y; v[2] = a.z; v[3] = a.w;
                v[4] = b.x; v[5] = b.y; v[6] = b.z; v[7] = b.w;
            } else {
#pragma unroll
                for (int i = 0; i < 8; i++) v[i] = 0.f;
            }
            uint4 hi, lo;
            split8(v, hi, lo);
            *(uint4*)(sAh + r * SA1 + k0) = hi;
            *(uint4*)(sAl + r * SA1 + k0) = lo;
        }
    }
#pragma unroll
    for (int i = 0; i < 8; i++) {
        int idx = i * 512 + t;
        int n   = idx >> 4;
        int k0  = (idx & 15) * 8;
        *(uint4*)(sBh + n * SA1 + k0) = *(const uint4*)(wh + n * DD + k0);
        *(uint4*)(sBl + n * SA1 + k0) = *(const uint4*)(wl + n * DD + k0);
    }
    __syncthreads();

    const int wm = wid & 3;
    const int wn = wid >> 2;

    float acc[2][8][4];
#pragma unroll
    for (int m = 0; m < 2; m++)
#pragma unroll
        for (int nf = 0; nf < 8; nf++)
#pragma unroll
            for (int j = 0; j < 4; j++) acc[m][nf][j] = 0.f;

#pragma unroll
    for (int ks = 0; ks < 8; ks++) {
        int k0 = ks * 16;
        uint32_t ah[2][4], al[2][4];
#pragma unroll
        for (int m = 0; m < 2; m++) {
            int r = wm * 32 + m * 16 + gid;
            ah[m][0] = *(const uint32_t*)(sAh + r * SA1 + k0 + q * 2);
            ah[m][1] = *(const uint32_t*)(sAh + (r + 8) * SA1 + k0 + q * 2);
            ah[m][2] = *(const uint32_t*)(sAh + r * SA1 + k0 + q * 2 + 8);
            ah[m][3] = *(const uint32_t*)(sAh + (r + 8) * SA1 + k0 + q * 2 + 8);
            al[m][0] = *(const uint32_t*)(sAl + r * SA1 + k0 + q * 2);
            al[m][1] = *(const uint32_t*)(sAl + (r + 8) * SA1 + k0 + q * 2);
            al[m][2] = *(const uint32_t*)(sAl + r * SA1 + k0 + q * 2 + 8);
            al[m][3] = *(const uint32_t*)(sAl + (r + 8) * SA1 + k0 + q * 2 + 8);
        }
#pragma unroll
        for (int nf = 0; nf < 8; nf++) {
            int      n = wn * 64 + nf * 8 + gid;
            uint32_t bh[2], bl[2];
            bh[0] = *(const uint32_t*)(sBh + n * SA1 + k0 + q * 2);
            bh[1] = *(const uint32_t*)(sBh + n * SA1 + k0 + q * 2 + 8);
            bl[0] = *(const uint32_t*)(sBl + n * SA1 + k0 + q * 2);
            bl[1] = *(const uint32_t*)(sBl + n * SA1 + k0 + q * 2 + 8);
#pragma unroll
            for (int m = 0; m < 2; m++) {
                mma16816(acc[m][nf], ah[m], bh);
                mma16816(acc[m][nf], ah[m], bl);
                mma16816(acc[m][nf], al[m], bh);
            }
        }
    }

#pragma unroll
    for (int nf = 0; nf < 8; nf++) {
        int    c  = wn * 64 + nf * 8 + q * 2;
        float2 b2 = *(const float2*)(bias + c);
        float  sx = 0.f, sy = 0.f, qx = 0.f, qy = 0.f;
#pragma unroll
        for (int m = 0; m < 2; m++) {
            int r = row0 + wm * 32 + m * 16 + gid;
            if (r < NN) {
                float vx = acc[m][nf][0] + b2.x;
                float vy = acc[m][nf][1] + b2.y;
                *(float2*)(g_y + (size_t)r * D2 + c) = make_float2(vx, vy);
                sx += vx; sy += vy; qx += vx * vx; qy += vy * vy;
            }
            if (r + 8 < NN) {
                float vx = acc[m][nf][2] + b2.x;
                float vy = acc[m][nf][3] + b2.y;
                *(float2*)(g_y + (size_t)(r + 8) * D2 + c) = make_float2(vx, vy);
                sx += vx; sy += vy; qx += vx * vx; qy += vy * vy;
            }
        }
#pragma unroll
        for (int o = 4; o < 32; o <<= 1) {
            sx += __shfl_xor_sync(0xffffffff, sx, o);
            sy += __shfl_xor_sync(0xffffffff, sy, o);
            qx += __shfl_xor_sync(0xffffffff, qx, o);
            qy += __shfl_xor_sync(0xffffffff, qy, o);
        }
        if (gid == 0) {
            atomicAdd(&g_stats[c], sx);
            atomicAdd(&g_stats[c + 1], sy);
            atomicAdd(&g_stats[256 + c], qx);
            atomicAdd(&g_stats[256 + c + 1], qy);
        }
    }
}

// =================================================================================
// GEMM2 (HMMA): v = relu(bn1(y)) @ W2 + b2, fused column stats. N=128, K=256.
// =================================================================================
#define SA2 264
#define G2_ALO 67584
#define G2_B 135168
#define G2_SMEM 202752

__global__ void __launch_bounds__(512, 1)
gemm2_tc(const float* __restrict__ bias, int layer) {
    extern __shared__ char sm[];
    __nv_bfloat16* sAh = (__nv_bfloat16*)sm;
    __nv_bfloat16* sAl = (__nv_bfloat16*)(sm + G2_ALO);
    __nv_bfloat16* sB  = (__nv_bfloat16*)(sm + G2_B);

    const __nv_bfloat16* wh = g_w2h + layer * 32768;
    const __nv_bfloat16* wl = g_w2l + layer * 32768;

    const int t    = threadIdx.x;
    const int lane = t & 31;
    const int wid  = t >> 5;
    const int row0 = blockIdx.x * 128;
    const int gid  = lane >> 2;
    const int q    = lane & 3;

    {
        int          r     = t >> 2;
        int          qq    = t & 3;
        const float* rp    = g_y + (size_t)(row0 + r) * D2;
        bool         valid = (row0 + r) < NN;
#pragma unroll
        for (int j = 0; j < 8; j++) {
            int   k0 = qq * 64 + j * 8;
            float v[8];
            if (valid) {
                float4 a = ((const float4*)rp)[k0 >> 2];
                float4 b = ((const float4*)rp)[(k0 >> 2) + 1];
                float  raw[8] = {a.x, a.y, a.z, a.w, b.x, b.y, b.z, b.w};
#pragma unroll
                for (int i = 0; i < 8; i++)
                    v[i] = fmaxf(raw[i] * g_sc[k0 + i] + g_sh[k0 + i], 0.f);
            } else {
#pragma unroll
                for (int i = 0; i < 8; i++) v[i] = 0.f;
            }
            uint4 hi, lo;
            split8(v, hi, lo);
            *(uint4*)(sAh + r * SA2 + k0) = hi;
            *(uint4*)(sAl + r * SA2 + k0) = lo;
        }
    }
#pragma unroll
    for (int i = 0; i < 8; i++) {
        int idx = i * 512 + t;
        int n   = idx >> 5;
        int k0  = (idx & 31) * 8;
        *(uint4*)(sB + n * SA2 + k0) = *(const uint4*)(wh + n * D2 + k0);
    }
    __syncthreads();

    const int wm = wid & 3;
    const int wn = wid >> 2;

    float acc[2][4][4];
#pragma unroll
    for (int m = 0; m < 2; m++)
#pragma unroll
        for (int nf = 0; nf < 4; nf++)
#pragma unroll
            for (int j = 0; j < 4; j++) acc[m][nf][j] = 0.f;

#pragma unroll
    for (int ks = 0; ks < 16; ks++) {
        int k0 = ks * 16;
        uint32_t ah[2][4], al[2][4];
#pragma unroll
        for (int m = 0; m < 2; m++) {
            int r = wm * 32 + m * 16 + gid;
            ah[m][0] = *(const uint32_t*)(sAh + r * SA2 + k0 + q * 2);
            ah[m][1] = *(const uint32_t*)(sAh + (r + 8) * SA2 + k0 + q * 2);
            ah[m][2] = *(const uint32_t*)(sAh + r * SA2 + k0 + q * 2 + 8);
            ah[m][3] = *(const uint32_t*)(sAh + (r + 8) * SA2 + k0 + q * 2 + 8);
            al[m][0] = *(const uint32_t*)(sAl + r * SA2 + k0 + q * 2);
            al[m][1] = *(const uint32_t*)(sAl + (r + 8) * SA2 + k0 + q * 2);
            al[m][2] = *(const uint32_t*)(sAl + r * SA2 + k0 + q * 2 + 8);
            al[m][3] = *(const uint32_t*)(sAl + (r + 8) * SA2 + k0 + q * 2 + 8);
        }
#pragma unroll
        for (int nf = 0; nf < 4; nf++) {
            int      n = wn * 32 + nf * 8 + gid;
            uint32_t bh[2];
            bh[0] = *(const uint32_t*)(sB + n * SA2 + k0 + q * 2);
            bh[1] = *(const uint32_t*)(sB + n * SA2 + k0 + q * 2 + 8);
#pragma unroll
            for (int m = 0; m < 2; m++) {
                mma16816(acc[m][nf], ah[m], bh);
                mma16816(acc[m][nf], al[m], bh);
            }
        }
    }

    __syncthreads();
#pragma unroll
    for (int i = 0; i < 8; i++) {
        int idx = i * 512 + t;
        int n   = idx >> 5;
        int k0  = (idx & 31) * 8;
        *(uint4*)(sB + n * SA2 + k0) = *(const uint4*)(wl + n * D2 + k0);
    }
    __syncthreads();

#pragma unroll
    for (int ks = 0; ks < 16; ks++) {
        int k0 = ks * 16;
        uint32_t ah[2][4];
#pragma unroll
        for (int m = 0; m < 2; m++) {
            int r = wm * 32 + m * 16 + gid;
            ah[m][0] = *(const uint32_t*)(sAh + r * SA2 + k0 + q * 2);
            ah[m][1] = *(const uint32_t*)(sAh + (r + 8) * SA2 + k0 + q * 2);
            ah[m][2] = *(const uint32_t*)(sAh + r * SA2 + k0 + q * 2 + 8);
            ah[m][3] = *(const uint32_t*)(sAh + (r + 8) * SA2 + k0 + q * 2 + 8);
        }
#pragma unroll
        for (int nf = 0; nf < 4; nf++) {
            int      n = wn * 32 + nf * 8 + gid;
            uint32_t bl[2];
            bl[0] = *(const uint32_t*)(sB + n * SA2 + k0 + q * 2);
            bl[1] = *(const uint32_t*)(sB + n * SA2 + k0 + q * 2 + 8);
#pragma unroll
            for (int m = 0; m < 2; m++) mma16816(acc[m][nf], ah[m], bl);
        }
    }

#pragma unroll
    for (int nf = 0; nf < 4; nf++) {
        int    c  = wn * 32 + nf * 8 + q * 2;
        float2 b2 = *(const float2*)(bias + c);
        float  sx = 0.f, sy = 0.f, qx = 0.f, qy = 0.f;
#pragma unroll
        for (int m = 0; m < 2; m++) {
            int r = row0 + wm * 32 + m * 16 + gid;
            if (r < NN) {
                float vx = acc[m][nf][0] + b2.x;
                float vy = acc[m][nf][1] + b2.y;
                *(float2*)(g_v + (size_t)r * DD + c) = make_float2(vx, vy);
                sx += vx; sy += vy; qx += vx * vx; qy += vy * vy;
            }
            if (r + 8 < NN) {
                float vx = acc[m][nf][2] + b2.x;
                float vy = acc[m][nf][3] + b2.y;
                *(float2*)(g_v + (size_t)(r + 8) * DD + c) = make_float2(vx, vy);
                sx += vx; sy += vy; qx += vx * vx; qy += vy * vy;
            }
        }
#pragma unroll
        for (int o = 4; o < 32; o <<= 1) {
            sx += __shfl_xor_sync(0xffffffff, sx, o);
            sy += __shfl_xor_sync(0xffffffff, sy, o);
            qx += __shfl_xor_sync(0xffffffff, qx, o);
            qy += __shfl_xor_sync(0xffffffff, qy, o);
        }
        if (gid == 0) {
            atomicAdd(&g_stats[c], sx);
            atomicAdd(&g_stats[c + 1], sy);
            atomicAdd(&g_stats[256 + c], qx);
            atomicAdd(&g_stats[256 + c + 1], qy);
        }
    }
}

// ---------------- finalize (self-zeroing) ----------------
__global__ void zero_stats_kernel() { g_stats[threadIdx.x] = 0.f; }

__global__ void finalize_kernel(const float* __restrict__ g, const float* __restrict__ be,
                                int ncols) {
    int c = threadIdx.x;  // 256 threads
    if (c < ncols) {
        float mu   = g_stats[c] * (1.f / NN);
        float var  = g_stats[256 + c] * (1.f / NN) - mu * mu;
        float istd = rsqrtf(var + 1e-5f);
        float s    = g[c] * istd;
        g_sc[c]    = s;
        g_sh[c]    = be[c] - mu * s;
    }
    g_stats[c]       = 0.f;
    g_stats[256 + c] = 0.f;
}

__global__ void norm_out_kernel(float* __restrict__ out) {
    int   i = blockIdx.x * blockDim.x + threadIdx.x;
    int   c = i & (DD - 1);
    out[i]  = g_v[i] * g_sc[c] + g_sh[c];
}

// ---------------- launch ----------------
extern "C" void kernel_launch(void* const* d_in, const int* in_sizes, int n_in,
                              void* d_out, int out_size) {
    const int*   x    = (const int*)d_in[0];
    const int*   ei   = (const int*)d_in[1];
    const int*   ea   = (const int*)d_in[2];
    const float* aemb = (const float*)d_in[3];
    const float* bemb = (const float*)d_in[4];
    const float* W1   = (const float*)d_in[5];
    const float* b1   = (const float*)d_in[6];
    const float* g1   = (const float*)d_in[7];
    const float* be1  = (const float*)d_in[8];
    const float* W2   = (const float*)d_in[9];
    const float* b2   = (const float*)d_in[10];
    const float* eps  = (const float*)d_in[11];
    const float* gout = (const float*)d_in[12];
    const float* beo  = (const float*)d_in[13];
    float*       out  = (float*)d_out;

    cudaFuncSetAttribute(gemm1_tc, cudaFuncAttributeMaxDynamicSharedMemorySize, G1_SMEM);
    cudaFuncSetAttribute(gemm2_tc, cudaFuncAttributeMaxDynamicSharedMemorySize, G2_SMEM);

    atom_enc_kernel<<<(NN * DD) / 256, 256>>>(x, aemb);
    zero_stats_kernel<<<1, 512>>>();
    wprep_all_kernel<<<640, 512>>>(W1, W2);

    const int NB = (NN + 511) / 512;
    zero_cnt_kernel<<<(NN + 255) / 256, 256>>>();
    hist_kernel<<<(NE + 255) / 256, 256>>>(ei);
    scan1_kernel<<<NB, 512>>>();
    scan2_kernel<<<1, 32>>>(NB);
    scan3_kernel<<<(NN + 255) / 256, 256>>>();
    fill_kernel<<<(NE + 255) / 256, 256>>>(ei, ea);

    const int mblocks = (NN + 127) / 128;
    const int gblocks = (NN + 63) / 64;
    for (int l = 0; l < NL; l++) {
        if (l == 0)
            gather_kernel<0><<<gblocks, 256>>>(bemb + l * 3 * 8 * DD, eps + l);
        else
            gather_kernel<1><<<gblocks, 256>>>(bemb + l * 3 * 8 * DD, eps + l);

        gemm1_tc<<<mblocks, 512, G1_SMEM>>>(b1 + l * D2, l);
        finalize_kernel<<<1, 256>>>(g1 + l * D2, be1 + l * D2, D2);

        gemm2_tc<<<mblocks, 512, G2_SMEM>>>(b2 + l * DD, l);
        finalize_kernel<<<1, 256>>>(gout + l * DD, beo + l * DD, DD);
    }
    norm_out_kernel<<<(NN * DD) / 256, 256>>>(out);
}